// round 1
// baseline (speedup 1.0000x reference)
#include <cuda_runtime.h>
#include <cstdint>

// Problem constants (from reference)
#define NUM_NODES 1000000
#define EMBED_DIM 200
#define NUM_LAYERS 3
#define NUM_WALKS 25
#define BATCH 8192
#define ROWS (1 + NUM_WALKS * NUM_LAYERS)   // 76 gathered rows per side
#define THREADS 224                          // 7 full warps; 200 active for dims

__global__ __launch_bounds__(THREADS, 8)
void gnp_score_kernel(const float* __restrict__ emb,
                      const float* __restrict__ layer_w,
                      const int*   __restrict__ uidx,
                      const int*   __restrict__ iidx,
                      const int*   __restrict__ uwalks,
                      const int*   __restrict__ iwalks,
                      float*       __restrict__ out)
{
    __shared__ int   s_uid[ROWS];
    __shared__ int   s_iid[ROWS];
    __shared__ float s_w[ROWS];
    __shared__ float s_red[THREADS / 32];

    const int b = blockIdx.x;
    const int t = threadIdx.x;

    // ---- stage per-row indices + softmax weights into SMEM ----
    if (t < ROWS) {
        // softmax over 4 layer weights (cheap, redundant per thread)
        float w0 = layer_w[0], w1 = layer_w[1], w2 = layer_w[2], w3 = layer_w[3];
        float m  = fmaxf(fmaxf(w0, w1), fmaxf(w2, w3));
        float e0 = __expf(w0 - m), e1 = __expf(w1 - m);
        float e2 = __expf(w2 - m), e3 = __expf(w3 - m);
        float inv = 1.0f / (e0 + e1 + e2 + e3);

        if (t == 0) {
            s_w[0]   = e0 * inv;           // base row weight
            s_uid[0] = uidx[b];
            s_iid[0] = iidx[b];
        } else {
            int w = (t - 1) / NUM_LAYERS;          // walk index 0..24
            int l = (t - 1) % NUM_LAYERS;          // layer-1 index 0..2
            float wl = (l == 0 ? e1 : (l == 1 ? e2 : e3)) * inv
                       * (1.0f / (float)NUM_WALKS);
            s_w[t] = wl;
            int off = (b * NUM_WALKS + w) * (NUM_LAYERS + 1) + (l + 1);
            s_uid[t] = uwalks[off];
            s_iid[t] = iwalks[off];
        }
    }
    __syncthreads();

    // ---- weighted gather-accumulate: each thread owns one dim ----
    float acc_u = 0.0f, acc_i = 0.0f;
    if (t < EMBED_DIM) {
        #pragma unroll 4
        for (int r = 0; r < ROWS; r++) {
            float w = s_w[r];
            size_t ou = (size_t)s_uid[r] * EMBED_DIM + t;
            size_t oi = (size_t)s_iid[r] * EMBED_DIM + t;
            acc_u = fmaf(w, __ldg(emb + ou), acc_u);
            acc_i = fmaf(w, __ldg(emb + oi), acc_i);
        }
    }

    // ---- dot-product block reduction (inactive threads contribute 0) ----
    float p = acc_u * acc_i;
    #pragma unroll
    for (int o = 16; o > 0; o >>= 1)
        p += __shfl_down_sync(0xffffffffu, p, o);
    if ((t & 31) == 0) s_red[t >> 5] = p;
    __syncthreads();

    if (t < 32) {
        float v = (t < (THREADS / 32)) ? s_red[t] : 0.0f;
        #pragma unroll
        for (int o = 16; o > 0; o >>= 1)
            v += __shfl_down_sync(0xffffffffu, v, o);
        if (t == 0) out[b] = v;
    }
}

extern "C" void kernel_launch(void* const* d_in, const int* in_sizes, int n_in,
                              void* d_out, int out_size)
{
    const float* emb     = (const float*)d_in[0];  // [1M, 200] f32
    const float* weights = (const float*)d_in[1];  // [4] f32
    const int*   uidx    = (const int*)  d_in[2];  // [8192] i32
    const int*   iidx    = (const int*)  d_in[3];  // [8192] i32
    const int*   uwalks  = (const int*)  d_in[4];  // [8192, 25, 4] i32
    const int*   iwalks  = (const int*)  d_in[5];  // [8192, 25, 4] i32
    float*       out     = (float*)d_out;          // [8192] f32

    gnp_score_kernel<<<BATCH, THREADS>>>(emb, weights, uidx, iidx,
                                         uwalks, iwalks, out);
}

// round 2
// speedup vs baseline: 1.0258x; 1.0258x over previous
#include <cuda_runtime.h>
#include <cstdint>

#define NUM_NODES 1000000
#define EMBED_DIM 200
#define NUM_LAYERS 3
#define NUM_WALKS 25
#define BATCH 8192
#define ROWS (1 + NUM_WALKS * NUM_LAYERS)   // 76 gathered rows per side
#define THREADS 256                          // warps 0-3: user side, 4-7: item side
#define HALF_DIM (EMBED_DIM / 2)             // 100 float2 per row

__global__ __launch_bounds__(THREADS, 8)
void gnp_score_kernel(const float* __restrict__ emb,
                      const float* __restrict__ layer_w,
                      const int*   __restrict__ uidx,
                      const int*   __restrict__ iidx,
                      const int*   __restrict__ uwalks,
                      const int*   __restrict__ iwalks,
                      float*       __restrict__ out)
{
    __shared__ int    s_id[2][ROWS];
    __shared__ float  s_w[ROWS];
    __shared__ float2 s_u[HALF_DIM];
    __shared__ float  s_red[THREADS / 32];

    const int b = blockIdx.x;
    const int t = threadIdx.x;

    // ---- stage indices for both sides (152 threads) ----
    if (t < 2 * ROWS) {
        int side = (t >= ROWS) ? 1 : 0;
        int r    = side ? (t - ROWS) : t;
        const int* walks = side ? iwalks : uwalks;
        const int* bidx  = side ? iidx   : uidx;
        if (r == 0) {
            s_id[side][0] = bidx[b];
        } else {
            int w = (r - 1) / NUM_LAYERS;
            int l = (r - 1) % NUM_LAYERS;
            s_id[side][r] = walks[(b * NUM_WALKS + w) * (NUM_LAYERS + 1) + (l + 1)];
        }
    }

    // ---- softmax weights (76 threads, redundant math is free) ----
    if (t < ROWS) {
        float w0 = layer_w[0], w1 = layer_w[1], w2 = layer_w[2], w3 = layer_w[3];
        float m  = fmaxf(fmaxf(w0, w1), fmaxf(w2, w3));
        float e0 = __expf(w0 - m), e1 = __expf(w1 - m);
        float e2 = __expf(w2 - m), e3 = __expf(w3 - m);
        float inv = 1.0f / (e0 + e1 + e2 + e3);
        if (t == 0) {
            s_w[0] = e0 * inv;
        } else {
            int l = (t - 1) % NUM_LAYERS;
            s_w[t] = (l == 0 ? e1 : (l == 1 ? e2 : e3)) * inv
                     * (1.0f / (float)NUM_WALKS);
        }
    }
    __syncthreads();

    // ---- weighted gather-accumulate, float2 per thread ----
    const int side = t >> 7;      // warps 0-3 -> user, 4-7 -> item
    const int j    = t & 127;     // 0..127; j<100 active

    float2 acc = make_float2(0.0f, 0.0f);
    if (j < HALF_DIM) {
        const float2* __restrict__ base = (const float2*)emb;
        const int* __restrict__ ids = s_id[side];
        #pragma unroll 4
        for (int r = 0; r < ROWS; r++) {
            float w = s_w[r];
            unsigned off = (unsigned)ids[r] * (unsigned)HALF_DIM + (unsigned)j;
            float2 v = __ldg(base + off);
            acc.x = fmaf(w, v.x, acc.x);
            acc.y = fmaf(w, v.y, acc.y);
        }
    }

    // ---- user side publishes its vector; item side forms the products ----
    if (side == 0 && j < HALF_DIM) s_u[j] = acc;
    __syncthreads();

    float p = 0.0f;
    if (side == 1 && j < HALF_DIM) {
        float2 u = s_u[j];
        p = u.x * acc.x + u.y * acc.y;
    }

    // ---- block reduction over all 256 threads ----
    #pragma unroll
    for (int o = 16; o > 0; o >>= 1)
        p += __shfl_down_sync(0xffffffffu, p, o);
    if ((t & 31) == 0) s_red[t >> 5] = p;
    __syncthreads();

    if (t < 32) {
        float v = (t < (THREADS / 32)) ? s_red[t] : 0.0f;
        #pragma unroll
        for (int o = 16; o > 0; o >>= 1)
            v += __shfl_down_sync(0xffffffffu, v, o);
        if (t == 0) out[b] = v;
    }
}

extern "C" void kernel_launch(void* const* d_in, const int* in_sizes, int n_in,
                              void* d_out, int out_size)
{
    const float* emb     = (const float*)d_in[0];  // [1M, 200] f32
    const float* weights = (const float*)d_in[1];  // [4] f32
    const int*   uidx    = (const int*)  d_in[2];  // [8192] i32
    const int*   iidx    = (const int*)  d_in[3];  // [8192] i32
    const int*   uwalks  = (const int*)  d_in[4];  // [8192, 25, 4] i32
    const int*   iwalks  = (const int*)  d_in[5];  // [8192, 25, 4] i32
    float*       out     = (float*)d_out;          // [8192] f32

    gnp_score_kernel<<<BATCH, THREADS>>>(emb, weights, uidx, iidx,
                                         uwalks, iwalks, out);
}

// round 3
// speedup vs baseline: 1.0787x; 1.0516x over previous
#include <cuda_runtime.h>
#include <cstdint>

#define NUM_NODES 1000000
#define EMBED_DIM 200
#define NUM_LAYERS 3
#define NUM_WALKS 25
#define BATCH 8192
#define ROWS (1 + NUM_WALKS * NUM_LAYERS)   // 76 gathered rows per side
#define THREADS 256
#define QUAD_DIM (EMBED_DIM / 4)            // 50 float4 per row
#define BPC 2                               // batch elements per CTA

__global__ __launch_bounds__(THREADS, 8)
void gnp_score_kernel(const float* __restrict__ emb,
                      const float* __restrict__ layer_w,
                      const int*   __restrict__ uidx,
                      const int*   __restrict__ iidx,
                      const int*   __restrict__ uwalks,
                      const int*   __restrict__ iwalks,
                      float*       __restrict__ out)
{
    // quadrant layout: q0 = (b0,user), q1 = (b0,item), q2 = (b1,user), q3 = (b1,item)
    __shared__ int    s_id[4][ROWS];
    __shared__ float  s_w[ROWS];
    __shared__ float4 s_u[BPC][QUAD_DIM];   // user-side accumulators
    __shared__ float  s_red[THREADS / 32];

    const int b0 = blockIdx.x * BPC;
    const int t  = threadIdx.x;

    // ---- stage indices for 4 quadrants (304 entries, grid-stride) ----
    for (int k = t; k < 4 * ROWS; k += THREADS) {
        int q    = k / ROWS;            // quadrant
        int r    = k % ROWS;
        int side = q & 1;               // 0=user 1=item
        int b    = b0 + (q >> 1);
        const int* walks = side ? iwalks : uwalks;
        const int* bidx  = side ? iidx   : uidx;
        if (r == 0) {
            s_id[q][0] = bidx[b];
        } else {
            int w = (r - 1) / NUM_LAYERS;
            int l = (r - 1) % NUM_LAYERS;
            s_id[q][r] = walks[(b * NUM_WALKS + w) * (NUM_LAYERS + 1) + (l + 1)];
        }
    }

    // ---- softmax weights (redundant per-thread math is free) ----
    if (t < ROWS) {
        float w0 = layer_w[0], w1 = layer_w[1], w2 = layer_w[2], w3 = layer_w[3];
        float m  = fmaxf(fmaxf(w0, w1), fmaxf(w2, w3));
        float e0 = __expf(w0 - m), e1 = __expf(w1 - m);
        float e2 = __expf(w2 - m), e3 = __expf(w3 - m);
        float inv = 1.0f / (e0 + e1 + e2 + e3);
        if (t == 0) {
            s_w[0] = e0 * inv;
        } else {
            int l = (t - 1) % NUM_LAYERS;
            s_w[t] = (l == 0 ? e1 : (l == 1 ? e2 : e3)) * inv
                     * (1.0f / (float)NUM_WALKS);
        }
    }
    __syncthreads();

    // ---- weighted gather-accumulate: float4 per thread ----
    const int q = t >> 6;          // quadrant 0..3
    const int j = t & 63;          // 0..63; j<50 active

    float4 acc = make_float4(0.f, 0.f, 0.f, 0.f);
    if (j < QUAD_DIM) {
        const float4* __restrict__ base = (const float4*)emb;
        const int* __restrict__ ids = s_id[q];
        #pragma unroll 4
        for (int r = 0; r < ROWS; r++) {
            float w = s_w[r];
            unsigned off = (unsigned)ids[r] * (unsigned)QUAD_DIM + (unsigned)j;
            float4 v = __ldg(base + off);
            acc.x = fmaf(w, v.x, acc.x);
            acc.y = fmaf(w, v.y, acc.y);
            acc.z = fmaf(w, v.z, acc.z);
            acc.w = fmaf(w, v.w, acc.w);
        }
    }

    // ---- user quadrants publish; item quadrants form products ----
    if (!(q & 1) && j < QUAD_DIM) s_u[q >> 1][j] = acc;
    __syncthreads();

    float p = 0.0f;
    if ((q & 1) && j < QUAD_DIM) {
        float4 u = s_u[q >> 1][j];
        p = u.x * acc.x + u.y * acc.y + u.z * acc.z + u.w * acc.w;
    }

    // ---- per-warp reduce, then combine warp pairs ----
    #pragma unroll
    for (int o = 16; o > 0; o >>= 1)
        p += __shfl_down_sync(0xffffffffu, p, o);
    if ((t & 31) == 0) s_red[t >> 5] = p;
    __syncthreads();

    // item quadrant q1 spans warps 2,3 -> out[b0]; q3 spans warps 6,7 -> out[b0+1]
    if (t == 0) out[b0]     = s_red[2] + s_red[3];
    if (t == 1) out[b0 + 1] = s_red[6] + s_red[7];
}

extern "C" void kernel_launch(void* const* d_in, const int* in_sizes, int n_in,
                              void* d_out, int out_size)
{
    const float* emb     = (const float*)d_in[0];  // [1M, 200] f32
    const float* weights = (const float*)d_in[1];  // [4] f32
    const int*   uidx    = (const int*)  d_in[2];  // [8192] i32
    const int*   iidx    = (const int*)  d_in[3];  // [8192] i32
    const int*   uwalks  = (const int*)  d_in[4];  // [8192, 25, 4] i32
    const int*   iwalks  = (const int*)  d_in[5];  // [8192, 25, 4] i32
    float*       out     = (float*)d_out;          // [8192] f32

    gnp_score_kernel<<<BATCH / BPC, THREADS>>>(emb, weights, uidx, iidx,
                                               uwalks, iwalks, out);
}